// round 1
// baseline (speedup 1.0000x reference)
#include <cuda_runtime.h>

#define NN 200000
#define NE 2000000
#define BB 1024
#define SEQL 1000
#define NVOC 26

// ---------------- scratch (static __device__, no allocs) ----------------
__device__ float g_h[NN * 32];
__device__ float g_agg[NN * 32];
__device__ float g_sum[32];
__device__ float g_ss[32];
__device__ float g_scale[32];
__device__ float g_shift[32];
__device__ float g_pooled[BB * 32];
__device__ float g_xc[BB * 256];
__device__ float g_t1[BB * 1024];
__device__ float g_t2[BB * 256];
__device__ float g_Wt[SEQL * 256];          // convW transposed: [c][(o,k)]
__device__ float g_G[256 * NVOC * 128];     // [(o*8+k)][v*128+j]
__device__ float g_H[SEQL * NVOC * 128];    // [(c*26+v)*128+j]
__device__ float g_cb[128];

// ---------------- layer-1 projection: z = x @ W1a, init h and agg ----------------
__global__ __launch_bounds__(256) void proj_kernel(const float* __restrict__ x,
                                                   const float* __restrict__ W,
                                                   float* __restrict__ h,
                                                   float* __restrict__ agg) {
    __shared__ float sW[78 * 32];
    int t = threadIdx.x;
    for (int i = t; i < 78 * 32; i += 256) sW[i] = W[i];
    __syncthreads();
    int node = blockIdx.x * 256 + t;
    if (node >= NN) return;
    float acc[32];
#pragma unroll
    for (int j = 0; j < 32; j++) acc[j] = 0.f;
    const float* xr = x + (long long)node * 78;
    for (int f = 0; f < 78; f++) {
        float xv = __ldg(xr + f);
#pragma unroll
        for (int j = 0; j < 32; j++) acc[j] += xv * sW[f * 32 + j];
    }
    float4* hp = (float4*)(h + node * 32);
    float4* ap = (float4*)(agg + node * 32);
#pragma unroll
    for (int q = 0; q < 8; q++) {
        float4 v = make_float4(acc[q * 4], acc[q * 4 + 1], acc[q * 4 + 2], acc[q * 4 + 3]);
        hp[q] = v; ap[q] = v;
    }
}

// ---------------- edge scatter: agg[dst] += h[src]  (8 threads / edge) ----------------
__global__ __launch_bounds__(256) void scatter_kernel(const float* __restrict__ h,
                                                      float* __restrict__ agg,
                                                      const int* __restrict__ src,
                                                      const int* __restrict__ dst) {
    if (blockIdx.x == 0 && threadIdx.x < 64) {  // zero BN stats for the following node pass
        if (threadIdx.x < 32) g_sum[threadIdx.x] = 0.f;
        else g_ss[threadIdx.x - 32] = 0.f;
    }
    int t = blockIdx.x * 256 + threadIdx.x;
    int e = t >> 3, q = t & 7;
    if (e < NE) {
        int s = __ldg(src + e), d = __ldg(dst + e);
        float4 v = ((const float4*)(h + s * 32))[q];
        float* p = agg + d * 32 + q * 4;
        atomicAdd(p + 0, v.x); atomicAdd(p + 1, v.y);
        atomicAdd(p + 2, v.z); atomicAdd(p + 3, v.w);
    }
}

// ---------------- per-node GIN MLP + relu + BN stats ----------------
// W1==nullptr => layer 1 (first matmul already folded into projection)
__global__ __launch_bounds__(256) void nodepass_kernel(const float* __restrict__ agg,
                                                       float* __restrict__ hout,
                                                       const float* __restrict__ W1,
                                                       const float* __restrict__ b1,
                                                       const float* __restrict__ W2,
                                                       const float* __restrict__ b2) {
    __shared__ float sW1[1024], sW2[1024], sb1[32], sb2[32];
    int t = threadIdx.x;
    if (W1) { for (int i = t; i < 1024; i += 256) sW1[i] = W1[i]; }
    for (int i = t; i < 1024; i += 256) sW2[i] = W2[i];
    if (t < 32) { sb1[t] = b1[t]; sb2[t] = b2[t]; }
    __syncthreads();
    int node = blockIdx.x * 256 + t;
    float r[32];
    if (node < NN) {
        float a[32];
        const float4* ap = (const float4*)(agg + node * 32);
#pragma unroll
        for (int q = 0; q < 8; q++) {
            float4 v = ap[q];
            a[q * 4] = v.x; a[q * 4 + 1] = v.y; a[q * 4 + 2] = v.z; a[q * 4 + 3] = v.w;
        }
        float t1[32];
        if (W1) {
#pragma unroll
            for (int j = 0; j < 32; j++) t1[j] = sb1[j];
#pragma unroll
            for (int f = 0; f < 32; f++) {
                float av = a[f];
#pragma unroll
                for (int j = 0; j < 32; j++) t1[j] += av * sW1[f * 32 + j];
            }
#pragma unroll
            for (int j = 0; j < 32; j++) t1[j] = fmaxf(t1[j], 0.f);
        } else {
#pragma unroll
            for (int j = 0; j < 32; j++) t1[j] = fmaxf(a[j] + sb1[j], 0.f);
        }
#pragma unroll
        for (int j = 0; j < 32; j++) r[j] = sb2[j];
#pragma unroll
        for (int f = 0; f < 32; f++) {
            float tv = t1[f];
#pragma unroll
            for (int j = 0; j < 32; j++) r[j] += tv * sW2[f * 32 + j];
        }
#pragma unroll
        for (int j = 0; j < 32; j++) r[j] = fmaxf(r[j], 0.f);
        float4* hp = (float4*)(hout + node * 32);
#pragma unroll
        for (int q = 0; q < 8; q++)
            hp[q] = make_float4(r[q * 4], r[q * 4 + 1], r[q * 4 + 2], r[q * 4 + 3]);
    } else {
#pragma unroll
        for (int j = 0; j < 32; j++) r[j] = 0.f;
    }
    int lane = t & 31;
#pragma unroll
    for (int j = 0; j < 32; j++) {
        float v = r[j], vv = v * v;
#pragma unroll
        for (int off = 16; off; off >>= 1) {
            v += __shfl_down_sync(0xffffffffu, v, off);
            vv += __shfl_down_sync(0xffffffffu, vv, off);
        }
        if (lane == 0) { atomicAdd(&g_sum[j], v); atomicAdd(&g_ss[j], vv); }
    }
}

// ---------------- BN finalize (and optional pooled zeroing) ----------------
__global__ void statsfin_kernel(const float* __restrict__ gamma,
                                const float* __restrict__ beta, int zero_pool) {
    if (blockIdx.x == 0 && threadIdx.x < 32) {
        int f = threadIdx.x;
        float m = g_sum[f] * (1.0f / (float)NN);
        float var = g_ss[f] * (1.0f / (float)NN) - m * m;
        float s = gamma[f] * rsqrtf(var + 1e-5f);
        g_scale[f] = s;
        g_shift[f] = beta[f] - m * s;
    }
    if (zero_pool) {
        int t = blockIdx.x * blockDim.x + threadIdx.x;
        for (int i = t; i < BB * 32; i += gridDim.x * blockDim.x) g_pooled[i] = 0.f;
    }
}

// ---------------- normalize h in place + copy into agg (next layer init) ----------------
__global__ __launch_bounds__(256) void normalize_kernel(float* __restrict__ h,
                                                        float* __restrict__ agg) {
    int i = blockIdx.x * 256 + threadIdx.x;  // float4 index
    if (i < NN * 8) {
        int q = i & 7;
        float4 v = ((float4*)h)[i];
        float4 sc = ((const float4*)g_scale)[q];
        float4 sh = ((const float4*)g_shift)[q];
        float4 o = make_float4(v.x * sc.x + sh.x, v.y * sc.y + sh.y,
                               v.z * sc.z + sh.z, v.w * sc.w + sh.w);
        ((float4*)h)[i] = o;
        ((float4*)agg)[i] = o;
    }
}

// ---------------- pooling: pooled[batch[i]] += normalize(h[i]) ----------------
__global__ __launch_bounds__(256) void pool_kernel(const float* __restrict__ h,
                                                   const int* __restrict__ batch) {
    int node = blockIdx.x * 256 + threadIdx.x;
    if (node >= NN) return;
    int b = __ldg(batch + node);
    float* pr = g_pooled + b * 32;
    const float4* hp = (const float4*)(h + node * 32);
#pragma unroll
    for (int q = 0; q < 8; q++) {
        float4 v = hp[q];
        float4 sc = ((const float4*)g_scale)[q];
        float4 sh = ((const float4*)g_shift)[q];
        atomicAdd(pr + q * 4 + 0, v.x * sc.x + sh.x);
        atomicAdd(pr + q * 4 + 1, v.y * sc.y + sh.y);
        atomicAdd(pr + q * 4 + 2, v.z * sc.z + sh.z);
        atomicAdd(pr + q * 4 + 3, v.w * sc.w + sh.w);
    }
}

// ---------------- generic tiled GEMM: C[M,N] = act(A[M,K] @ B[K,N] + bias) ----------------
// K multiple of 16, N multiple of 64 (true for every call site); M guarded.
__global__ __launch_bounds__(256) void gemm64_kernel(const float* __restrict__ A,
                                                     const float* __restrict__ B,
                                                     const float* __restrict__ bias,
                                                     float* __restrict__ C,
                                                     int M, int N, int K, int ldc, int doRelu) {
    __shared__ float As[16][68];
    __shared__ float Bs[16][68];
    int tx = threadIdx.x & 15, ty = threadIdx.x >> 4;
    int m0 = blockIdx.y * 64, n0 = blockIdx.x * 64;
    int la_m = threadIdx.x >> 2;
    int la_k = (threadIdx.x & 3) * 4;
    int lb_k = threadIdx.x >> 4;
    int lb_n = (threadIdx.x & 15) * 4;
    float acc[4][4];
#pragma unroll
    for (int r = 0; r < 4; r++)
#pragma unroll
        for (int c = 0; c < 4; c++) acc[r][c] = 0.f;

    for (int k0 = 0; k0 < K; k0 += 16) {
        float4 av = make_float4(0.f, 0.f, 0.f, 0.f);
        if (m0 + la_m < M) av = *(const float4*)(A + (long long)(m0 + la_m) * K + k0 + la_k);
        As[la_k + 0][la_m] = av.x; As[la_k + 1][la_m] = av.y;
        As[la_k + 2][la_m] = av.z; As[la_k + 3][la_m] = av.w;
        float4 bv = *(const float4*)(B + (long long)(k0 + lb_k) * N + n0 + lb_n);
        *(float4*)&Bs[lb_k][lb_n] = bv;
        __syncthreads();
#pragma unroll
        for (int kk = 0; kk < 16; kk++) {
            float4 a4 = *(const float4*)&As[kk][ty * 4];
            float4 b4 = *(const float4*)&Bs[kk][tx * 4];
            acc[0][0] += a4.x * b4.x; acc[0][1] += a4.x * b4.y; acc[0][2] += a4.x * b4.z; acc[0][3] += a4.x * b4.w;
            acc[1][0] += a4.y * b4.x; acc[1][1] += a4.y * b4.y; acc[1][2] += a4.y * b4.z; acc[1][3] += a4.y * b4.w;
            acc[2][0] += a4.z * b4.x; acc[2][1] += a4.z * b4.y; acc[2][2] += a4.z * b4.z; acc[2][3] += a4.z * b4.w;
            acc[3][0] += a4.w * b4.x; acc[3][1] += a4.w * b4.y; acc[3][2] += a4.w * b4.z; acc[3][3] += a4.w * b4.w;
        }
        __syncthreads();
    }
#pragma unroll
    for (int r = 0; r < 4; r++) {
        int row = m0 + ty * 4 + r;
        if (row >= M) continue;
#pragma unroll
        for (int c = 0; c < 4; c++) {
            int col = n0 + tx * 4 + c;
            float v = acc[r][c];
            if (bias) v += __ldg(bias + col);
            if (doRelu) v = fmaxf(v, 0.f);
            C[(long long)row * ldc + col] = v;
        }
    }
}

// ---------------- protein branch precomputes ----------------
// Wt[c][(o*8+k)] = convW[o][c][k]
__global__ void wtrans_kernel(const float* __restrict__ convW) {
    int i = blockIdx.x * 256 + threadIdx.x;
    if (i < SEQL * 256) {
        int c = i >> 8, ok = i & 255, o = ok >> 3, k = ok & 7;
        g_Wt[i] = convW[o * 8000 + c * 8 + k];
    }
}

// G[(o*8+k)][v*128+j] = sum_l emb[v][l+k] * Fw[(o*121+l)*128 + j]
__global__ __launch_bounds__(1024) void g_kernel(const float* __restrict__ emb,
                                                 const float* __restrict__ Fw) {
    int o = blockIdx.x, v = blockIdx.y;
    int j = threadIdx.x, k = threadIdx.y;  // (128, 8)
    __shared__ float E[128];
    if (threadIdx.y == 0) E[j] = emb[v * 128 + j];
    __syncthreads();
    float acc = 0.f;
    const float* fp = Fw + (long long)(o * 121) * 128 + j;
#pragma unroll 11
    for (int l = 0; l < 121; l++) acc += E[l + k] * fp[l * 128];
    g_G[(o * 8 + k) * (NVOC * 128) + v * 128 + j] = acc;
}

// cb[j] = fcxt_b[j] + sum_o convb[o] * sum_l Fw[(o*121+l)*128+j]
__global__ void cb_kernel(const float* __restrict__ Fw, const float* __restrict__ convb,
                          const float* __restrict__ fcxt_b) {
    int j = threadIdx.x;
    float acc = fcxt_b[j];
    for (int o = 0; o < 32; o++) {
        float fs = 0.f;
        for (int l = 0; l < 121; l++) fs += Fw[(long long)(o * 121 + l) * 128 + j];
        acc += convb[o] * fs;
    }
    g_cb[j] = acc;
}

// xt[b][j] = sum_c H[c][target[b,c]][j] + cb[j]  -> xc[b][128+j]
__global__ __launch_bounds__(128) void xt_kernel(const int* __restrict__ target) {
    __shared__ int ts[SEQL];
    int b = blockIdx.x, j = threadIdx.x;
    for (int c = j; c < SEQL; c += 128) ts[c] = target[(long long)b * SEQL + c];
    __syncthreads();
    float acc = 0.f;
#pragma unroll 8
    for (int c = 0; c < SEQL; c++) {
        int v = ts[c];
        acc += __ldg(&g_H[(long long)(c * NVOC + v) * 128 + j]);
    }
    g_xc[b * 256 + 128 + j] = acc + g_cb[j];
}

// ---------------- final dot: out[row] = t2[row] . out_W + out_b ----------------
__global__ void out_kernel(const float* __restrict__ W, const float* __restrict__ b,
                           float* __restrict__ out) {
    int row = blockIdx.x * 8 + (threadIdx.x >> 5);
    int lane = threadIdx.x & 31;
    if (row >= BB) return;
    float acc = 0.f;
    for (int i = lane; i < 256; i += 32) acc += g_t2[row * 256 + i] * __ldg(W + i);
#pragma unroll
    for (int off = 16; off; off >>= 1) acc += __shfl_down_sync(0xffffffffu, acc, off);
    if (lane == 0) out[row] = acc + __ldg(b);
}

// ---------------- launch ----------------
extern "C" void kernel_launch(void* const* d_in, const int* in_sizes, int n_in,
                              void* d_out, int out_size) {
    const float* x      = (const float*)d_in[0];
    const int*   ei     = (const int*)d_in[1];
    const int*   src    = ei;
    const int*   dst    = ei + NE;
    const int*   batch  = (const int*)d_in[2];
    const int*   target = (const int*)d_in[3];
    const float* W1a = (const float*)d_in[4];
    const float* b1a = (const float*)d_in[5];
    const float* W2a = (const float*)d_in[6];
    const float* b2a = (const float*)d_in[7];
    const float* g1  = (const float*)d_in[8];
    const float* be1 = (const float*)d_in[9];
    const float* Ws1 = (const float*)d_in[10];
    const float* bs1 = (const float*)d_in[11];
    const float* Ws2 = (const float*)d_in[12];
    const float* bs2 = (const float*)d_in[13];
    const float* gs  = (const float*)d_in[14];
    const float* bes = (const float*)d_in[15];
    const float* fc1xd_W = (const float*)d_in[16];
    const float* fc1xd_b = (const float*)d_in[17];
    const float* emb     = (const float*)d_in[18];
    const float* convW   = (const float*)d_in[19];
    const float* convb   = (const float*)d_in[20];
    const float* fcxt_W  = (const float*)d_in[21];
    const float* fcxt_b  = (const float*)d_in[22];
    const float* fc1_W   = (const float*)d_in[23];
    const float* fc1_b   = (const float*)d_in[24];
    const float* fc2_W   = (const float*)d_in[25];
    const float* fc2_b   = (const float*)d_in[26];
    const float* out_W   = (const float*)d_in[27];
    const float* out_b   = (const float*)d_in[28];

    float *p_h, *p_agg, *p_pooled, *p_xc, *p_t1, *p_t2, *p_Wt, *p_G, *p_H;
    cudaGetSymbolAddress((void**)&p_h, g_h);
    cudaGetSymbolAddress((void**)&p_agg, g_agg);
    cudaGetSymbolAddress((void**)&p_pooled, g_pooled);
    cudaGetSymbolAddress((void**)&p_xc, g_xc);
    cudaGetSymbolAddress((void**)&p_t1, g_t1);
    cudaGetSymbolAddress((void**)&p_t2, g_t2);
    cudaGetSymbolAddress((void**)&p_Wt, g_Wt);
    cudaGetSymbolAddress((void**)&p_G, g_G);
    cudaGetSymbolAddress((void**)&p_H, g_H);

    const int NODE_BLOCKS = (NN + 255) / 256;       // 782
    const int SCAT_BLOCKS = (NE * 8) / 256;         // 62500
    const int NORM_BLOCKS = (NN * 8) / 256;         // 6250

    // ---- protein branch precomputes (independent of graph) ----
    wtrans_kernel<<<(SEQL * 256 + 255) / 256, 256>>>(convW);
    g_kernel<<<dim3(32, NVOC), dim3(128, 8)>>>(emb, fcxt_W);
    cb_kernel<<<1, 128>>>(fcxt_W, convb, fcxt_b);
    gemm64_kernel<<<dim3((NVOC * 128) / 64, (SEQL + 63) / 64), 256>>>(
        p_Wt, p_G, nullptr, p_H, SEQL, NVOC * 128, 256, NVOC * 128, 0);
    xt_kernel<<<BB, 128>>>(target);

    // ---- graph: layer 1 ----
    proj_kernel<<<NODE_BLOCKS, 256>>>(x, W1a, p_h, p_agg);
    scatter_kernel<<<SCAT_BLOCKS, 256>>>(p_h, p_agg, src, dst);
    nodepass_kernel<<<NODE_BLOCKS, 256>>>(p_agg, p_h, nullptr, b1a, W2a, b2a);
    statsfin_kernel<<<1, 32>>>(g1, be1, 0);

    // ---- graph: layers 2..5 ----
    for (int i = 0; i < 4; i++) {
        normalize_kernel<<<NORM_BLOCKS, 256>>>(p_h, p_agg);
        scatter_kernel<<<SCAT_BLOCKS, 256>>>(p_h, p_agg, src, dst);
        nodepass_kernel<<<NODE_BLOCKS, 256>>>(p_agg, p_h, Ws1 + i * 1024, bs1 + i * 32,
                                              Ws2 + i * 1024, bs2 + i * 32);
        if (i == 3) statsfin_kernel<<<64, 512>>>(gs + i * 32, bes + i * 32, 1);
        else        statsfin_kernel<<<1, 32>>>(gs + i * 32, bes + i * 32, 0);
    }

    // ---- pooling + drug head (xc[:, :128]) ----
    pool_kernel<<<NODE_BLOCKS, 256>>>(p_h, batch);
    gemm64_kernel<<<dim3(128 / 64, BB / 64), 256>>>(p_pooled, fc1xd_W, fc1xd_b,
                                                    p_xc, BB, 128, 32, 256, 1);

    // ---- joint head ----
    gemm64_kernel<<<dim3(1024 / 64, BB / 64), 256>>>(p_xc, fc1_W, fc1_b, p_t1, BB, 1024, 256, 1024, 1);
    gemm64_kernel<<<dim3(256 / 64, BB / 64), 256>>>(p_t1, fc2_W, fc2_b, p_t2, BB, 256, 1024, 256, 1);
    out_kernel<<<BB / 8, 256>>>(out_W, out_b, (float*)d_out);
}

// round 3
// speedup vs baseline: 2.3574x; 2.3574x over previous
#include <cuda_runtime.h>

#define NN 200000
#define NE 2000000
#define BB 1024
#define SEQL 1000
#define NVOC 26
#define NBLK ((NN + 255) / 256)   // 782

// ---------------- scratch (static __device__, no allocs) ----------------
__device__ float g_h[NN * 32];
__device__ float g_agg[NN * 32];
__device__ float g_sum[32];
__device__ float g_ss[32];
__device__ float g_scale[32];
__device__ float g_shift[32];
__device__ float g_pooled[BB * 32];
__device__ float g_xc[BB * 256];
__device__ float g_t1[BB * 1024];
__device__ float g_t2[BB * 256];
__device__ float g_Wt[SEQL * 256];          // convW transposed: [c][(o,k)]
__device__ float g_G[256 * NVOC * 128];     // [(o*8+k)][v*128+j]
__device__ float g_H[SEQL * NVOC * 128];    // [(c*26+v)*128+j]
__device__ float g_cb[128];
// CSR scratch
__device__ int g_row[NN + 1];
__device__ int g_cur[NN];                   // histogram counts, then fill cursor
__device__ int g_col[NE];
__device__ int g_bsums[NBLK + 2];

// ================= CSR build =================
__global__ __launch_bounds__(256) void zero_cnt_kernel() {
    int i = blockIdx.x * 256 + threadIdx.x;
    if (i < NN) g_cur[i] = 0;
}

__global__ __launch_bounds__(256) void hist_kernel(const int* __restrict__ dst) {
    int e = blockIdx.x * 256 + threadIdx.x;
    if (e < NE) atomicAdd(&g_cur[__ldg(dst + e)], 1);
}

__global__ __launch_bounds__(256) void scan1_kernel() {
    __shared__ int s[256];
    int t = threadIdx.x;
    int i = blockIdx.x * 256 + t;
    int v = (i < NN) ? g_cur[i] : 0;
    s[t] = v;
    __syncthreads();
    for (int off = 1; off < 256; off <<= 1) {
        int x = (t >= off) ? s[t - off] : 0;
        __syncthreads();
        s[t] += x;
        __syncthreads();
    }
    if (i < NN) g_row[i] = s[t] - v;   // local exclusive
    if (t == 255) g_bsums[blockIdx.x] = s[255];
}

__global__ __launch_bounds__(1024) void scan2_kernel() {
    __shared__ int s[1024];
    int t = threadIdx.x;
    int v = (t < NBLK) ? g_bsums[t] : 0;
    s[t] = v;
    __syncthreads();
    for (int off = 1; off < 1024; off <<= 1) {
        int x = (t >= off) ? s[t - off] : 0;
        __syncthreads();
        s[t] += x;
        __syncthreads();
    }
    if (t < NBLK) g_bsums[t] = s[t] - v;
}

__global__ __launch_bounds__(256) void scan3_kernel() {
    int i = blockIdx.x * 256 + threadIdx.x;
    if (i < NN) {
        int r = g_row[i] + g_bsums[blockIdx.x];
        g_row[i] = r;
        g_cur[i] = r;   // fill cursor
    }
    if (i == 0) g_row[NN] = NE;
}

__global__ __launch_bounds__(256) void fill_kernel(const int* __restrict__ src,
                                                   const int* __restrict__ dst) {
    int e = blockIdx.x * 256 + threadIdx.x;
    if (e < NE) {
        int d = __ldg(dst + e);
        int pos = atomicAdd(&g_cur[d], 1);
        g_col[pos] = __ldg(src + e);
    }
}

// ---------------- layer-1 projection: z = x @ W1a ----------------
__global__ __launch_bounds__(256) void proj_kernel(const float* __restrict__ x,
                                                   const float* __restrict__ W,
                                                   float* __restrict__ h) {
    __shared__ float sW[78 * 32];
    int t = threadIdx.x;
    for (int i = t; i < 78 * 32; i += 256) sW[i] = W[i];
    __syncthreads();
    int node = blockIdx.x * 256 + t;
    if (node >= NN) return;
    float acc[32];
#pragma unroll
    for (int j = 0; j < 32; j++) acc[j] = 0.f;
    const float* xr = x + (long long)node * 78;
    for (int f = 0; f < 78; f++) {
        float xv = __ldg(xr + f);
#pragma unroll
        for (int j = 0; j < 32; j++) acc[j] += xv * sW[f * 32 + j];
    }
    float4* hp = (float4*)(h + node * 32);
#pragma unroll
    for (int q = 0; q < 8; q++)
        hp[q] = make_float4(acc[q * 4], acc[q * 4 + 1], acc[q * 4 + 2], acc[q * 4 + 3]);
}

// ---------------- CSR gather aggregation (+ fused BN affine of previous layer) ------
__global__ __launch_bounds__(256) void agg_kernel(const float* __restrict__ h,
                                                  float* __restrict__ agg, int useNorm) {
    if (blockIdx.x == 0 && threadIdx.x < 64) {   // zero BN stats for following passes
        if (threadIdx.x < 32) g_sum[threadIdx.x] = 0.f;
        else g_ss[threadIdx.x - 32] = 0.f;
    }
    int gid = blockIdx.x * 256 + threadIdx.x;
    int node = gid >> 3, q = gid & 7;
    if (node >= NN) return;
    int beg = g_row[node], end = g_row[node + 1];
    float4 acc = ((const float4*)(h + node * 32))[q];
    for (int e = beg; e < end; e++) {
        int s = __ldg(&g_col[e]);
        float4 v = __ldg((const float4*)(h + s * 32) + q);
        acc.x += v.x; acc.y += v.y; acc.z += v.z; acc.w += v.w;
    }
    if (useNorm) {
        float4 sc = ((const float4*)g_scale)[q];
        float4 sh = ((const float4*)g_shift)[q];
        float cnt = (float)(end - beg + 1);
        acc.x = sc.x * acc.x + cnt * sh.x;
        acc.y = sc.y * acc.y + cnt * sh.y;
        acc.z = sc.z * acc.z + cnt * sh.z;
        acc.w = sc.w * acc.w + cnt * sh.w;
    }
    ((float4*)(agg + node * 32))[q] = acc;
}

// ---------------- per-node GIN MLP + relu ----------------
__global__ __launch_bounds__(256) void nodepass_kernel(const float* __restrict__ agg,
                                                       float* __restrict__ hout,
                                                       const float* __restrict__ W1,
                                                       const float* __restrict__ b1,
                                                       const float* __restrict__ W2,
                                                       const float* __restrict__ b2) {
    __shared__ float sW1[1024], sW2[1024], sb1[32], sb2[32];
    int t = threadIdx.x;
    if (W1) { for (int i = t; i < 1024; i += 256) sW1[i] = W1[i]; }
    for (int i = t; i < 1024; i += 256) sW2[i] = W2[i];
    if (t < 32) { sb1[t] = b1[t]; sb2[t] = b2[t]; }
    __syncthreads();
    int node = blockIdx.x * 256 + t;
    if (node >= NN) return;
    float a[32];
    const float4* ap = (const float4*)(agg + node * 32);
#pragma unroll
    for (int q = 0; q < 8; q++) {
        float4 v = ap[q];
        a[q * 4] = v.x; a[q * 4 + 1] = v.y; a[q * 4 + 2] = v.z; a[q * 4 + 3] = v.w;
    }
    float t1[32];
    if (W1) {
#pragma unroll
        for (int j = 0; j < 32; j++) t1[j] = sb1[j];
#pragma unroll
        for (int f = 0; f < 32; f++) {
            float av = a[f];
#pragma unroll
            for (int j = 0; j < 32; j++) t1[j] += av * sW1[f * 32 + j];
        }
#pragma unroll
        for (int j = 0; j < 32; j++) t1[j] = fmaxf(t1[j], 0.f);
    } else {
#pragma unroll
        for (int j = 0; j < 32; j++) t1[j] = fmaxf(a[j] + sb1[j], 0.f);
    }
    float r[32];
#pragma unroll
    for (int j = 0; j < 32; j++) r[j] = sb2[j];
#pragma unroll
    for (int f = 0; f < 32; f++) {
        float tv = t1[f];
#pragma unroll
        for (int j = 0; j < 32; j++) r[j] += tv * sW2[f * 32 + j];
    }
    float4* hp = (float4*)(hout + node * 32);
#pragma unroll
    for (int q = 0; q < 8; q++)
        hp[q] = make_float4(fmaxf(r[q * 4], 0.f), fmaxf(r[q * 4 + 1], 0.f),
                            fmaxf(r[q * 4 + 2], 0.f), fmaxf(r[q * 4 + 3], 0.f));
}

// ---------------- BN column sums ----------------
__global__ __launch_bounds__(256) void colsum_kernel(const float* __restrict__ h) {
    __shared__ float rs[8][33], rss[8][33];
    int f = threadIdx.x & 31, sub = threadIdx.x >> 5;
    float s = 0.f, ss = 0.f;
    for (int row = blockIdx.x * 8 + sub; row < NN; row += gridDim.x * 8) {
        float v = __ldg(h + row * 32 + f);
        s += v; ss += v * v;
    }
    rs[sub][f] = s; rss[sub][f] = ss;
    __syncthreads();
    if (threadIdx.x < 32) {
        float a = 0.f, b = 0.f;
#pragma unroll
        for (int k = 0; k < 8; k++) { a += rs[k][f]; b += rss[k][f]; }
        atomicAdd(&g_sum[f], a);
        atomicAdd(&g_ss[f], b);
    }
}

// ---------------- BN finalize (and optional pooled zeroing) ----------------
__global__ void statsfin_kernel(const float* __restrict__ gamma,
                                const float* __restrict__ beta, int zero_pool) {
    if (blockIdx.x == 0 && threadIdx.x < 32) {
        int f = threadIdx.x;
        float m = g_sum[f] * (1.0f / (float)NN);
        float var = g_ss[f] * (1.0f / (float)NN) - m * m;
        float s = gamma[f] * rsqrtf(var + 1e-5f);
        g_scale[f] = s;
        g_shift[f] = beta[f] - m * s;
    }
    if (zero_pool) {
        int t = blockIdx.x * blockDim.x + threadIdx.x;
        for (int i = t; i < BB * 32; i += gridDim.x * blockDim.x) g_pooled[i] = 0.f;
    }
}

// ---------------- pooling ----------------
__global__ __launch_bounds__(256) void pool_kernel(const float* __restrict__ h,
                                                   const int* __restrict__ batch) {
    int node = blockIdx.x * 256 + threadIdx.x;
    if (node >= NN) return;
    int b = __ldg(batch + node);
    float* pr = g_pooled + b * 32;
    const float4* hp = (const float4*)(h + node * 32);
#pragma unroll
    for (int q = 0; q < 8; q++) {
        float4 v = hp[q];
        float4 sc = ((const float4*)g_scale)[q];
        float4 sh = ((const float4*)g_shift)[q];
        atomicAdd(pr + q * 4 + 0, v.x * sc.x + sh.x);
        atomicAdd(pr + q * 4 + 1, v.y * sc.y + sh.y);
        atomicAdd(pr + q * 4 + 2, v.z * sc.z + sh.z);
        atomicAdd(pr + q * 4 + 3, v.w * sc.w + sh.w);
    }
}

// ---------------- generic tiled GEMM ----------------
__global__ __launch_bounds__(256) void gemm64_kernel(const float* __restrict__ A,
                                                     const float* __restrict__ B,
                                                     const float* __restrict__ bias,
                                                     float* __restrict__ C,
                                                     int M, int N, int K, int ldc, int doRelu) {
    __shared__ float As[16][68];
    __shared__ float Bs[16][68];
    int tx = threadIdx.x & 15, ty = threadIdx.x >> 4;
    int m0 = blockIdx.y * 64, n0 = blockIdx.x * 64;
    int la_m = threadIdx.x >> 2;
    int la_k = (threadIdx.x & 3) * 4;
    int lb_k = threadIdx.x >> 4;
    int lb_n = (threadIdx.x & 15) * 4;
    float acc[4][4];
#pragma unroll
    for (int r = 0; r < 4; r++)
#pragma unroll
        for (int c = 0; c < 4; c++) acc[r][c] = 0.f;

    for (int k0 = 0; k0 < K; k0 += 16) {
        float4 av = make_float4(0.f, 0.f, 0.f, 0.f);
        if (m0 + la_m < M) av = *(const float4*)(A + (long long)(m0 + la_m) * K + k0 + la_k);
        As[la_k + 0][la_m] = av.x; As[la_k + 1][la_m] = av.y;
        As[la_k + 2][la_m] = av.z; As[la_k + 3][la_m] = av.w;
        float4 bv = *(const float4*)(B + (long long)(k0 + lb_k) * N + n0 + lb_n);
        *(float4*)&Bs[lb_k][lb_n] = bv;
        __syncthreads();
#pragma unroll
        for (int kk = 0; kk < 16; kk++) {
            float4 a4 = *(const float4*)&As[kk][ty * 4];
            float4 b4 = *(const float4*)&Bs[kk][tx * 4];
            acc[0][0] += a4.x * b4.x; acc[0][1] += a4.x * b4.y; acc[0][2] += a4.x * b4.z; acc[0][3] += a4.x * b4.w;
            acc[1][0] += a4.y * b4.x; acc[1][1] += a4.y * b4.y; acc[1][2] += a4.y * b4.z; acc[1][3] += a4.y * b4.w;
            acc[2][0] += a4.z * b4.x; acc[2][1] += a4.z * b4.y; acc[2][2] += a4.z * b4.z; acc[2][3] += a4.z * b4.w;
            acc[3][0] += a4.w * b4.x; acc[3][1] += a4.w * b4.y; acc[3][2] += a4.w * b4.z; acc[3][3] += a4.w * b4.w;
        }
        __syncthreads();
    }
#pragma unroll
    for (int r = 0; r < 4; r++) {
        int row = m0 + ty * 4 + r;
        if (row >= M) continue;
#pragma unroll
        for (int c = 0; c < 4; c++) {
            int col = n0 + tx * 4 + c;
            float v = acc[r][c];
            if (bias) v += __ldg(bias + col);
            if (doRelu) v = fmaxf(v, 0.f);
            C[(long long)row * ldc + col] = v;
        }
    }
}

// ---------------- protein branch precomputes ----------------
__global__ void wtrans_kernel(const float* __restrict__ convW) {
    int i = blockIdx.x * 256 + threadIdx.x;
    if (i < SEQL * 256) {
        int c = i >> 8, ok = i & 255, o = ok >> 3, k = ok & 7;
        g_Wt[i] = convW[o * 8000 + c * 8 + k];
    }
}

__global__ __launch_bounds__(1024) void g_kernel(const float* __restrict__ emb,
                                                 const float* __restrict__ Fw) {
    int o = blockIdx.x, v = blockIdx.y;
    int j = threadIdx.x, k = threadIdx.y;  // (128, 8)
    __shared__ float E[128];
    if (threadIdx.y == 0) E[j] = emb[v * 128 + j];
    __syncthreads();
    float acc = 0.f;
    const float* fp = Fw + (long long)(o * 121) * 128 + j;
#pragma unroll 11
    for (int l = 0; l < 121; l++) acc += E[l + k] * fp[l * 128];
    g_G[(o * 8 + k) * (NVOC * 128) + v * 128 + j] = acc;
}

__global__ void cb_kernel(const float* __restrict__ Fw, const float* __restrict__ convb,
                          const float* __restrict__ fcxt_b) {
    int j = threadIdx.x;
    float acc = fcxt_b[j];
    for (int o = 0; o < 32; o++) {
        float fs = 0.f;
        for (int l = 0; l < 121; l++) fs += Fw[(long long)(o * 121 + l) * 128 + j];
        acc += convb[o] * fs;
    }
    g_cb[j] = acc;
}

__global__ __launch_bounds__(128) void xt_kernel(const int* __restrict__ target) {
    __shared__ int ts[SEQL];
    int b = blockIdx.x, j = threadIdx.x;
    for (int c = j; c < SEQL; c += 128) ts[c] = target[(long long)b * SEQL + c];
    __syncthreads();
    float acc = 0.f;
#pragma unroll 8
    for (int c = 0; c < SEQL; c++) {
        int v = ts[c];
        acc += __ldg(&g_H[(long long)(c * NVOC + v) * 128 + j]);
    }
    g_xc[b * 256 + 128 + j] = acc + g_cb[j];
}

__global__ void out_kernel(const float* __restrict__ W, const float* __restrict__ b,
                           float* __restrict__ out) {
    int row = blockIdx.x * 8 + (threadIdx.x >> 5);
    int lane = threadIdx.x & 31;
    if (row >= BB) return;
    float acc = 0.f;
    for (int i = lane; i < 256; i += 32) acc += g_t2[row * 256 + i] * __ldg(W + i);
#pragma unroll
    for (int off = 16; off; off >>= 1) acc += __shfl_down_sync(0xffffffffu, acc, off);
    if (lane == 0) out[row] = acc + __ldg(b);
}

// ---------------- launch ----------------
extern "C" void kernel_launch(void* const* d_in, const int* in_sizes, int n_in,
                              void* d_out, int out_size) {
    const float* x      = (const float*)d_in[0];
    const int*   ei     = (const int*)d_in[1];
    const int*   src    = ei;
    const int*   dst    = ei + NE;
    const int*   batch  = (const int*)d_in[2];
    const int*   target = (const int*)d_in[3];
    const float* W1a = (const float*)d_in[4];
    const float* b1a = (const float*)d_in[5];
    const float* W2a = (const float*)d_in[6];
    const float* b2a = (const float*)d_in[7];
    const float* g1  = (const float*)d_in[8];
    const float* be1 = (const float*)d_in[9];
    const float* Ws1 = (const float*)d_in[10];
    const float* bs1 = (const float*)d_in[11];
    const float* Ws2 = (const float*)d_in[12];
    const float* bs2 = (const float*)d_in[13];
    const float* gs  = (const float*)d_in[14];
    const float* bes = (const float*)d_in[15];
    const float* fc1xd_W = (const float*)d_in[16];
    const float* fc1xd_b = (const float*)d_in[17];
    const float* emb     = (const float*)d_in[18];
    const float* convW   = (const float*)d_in[19];
    const float* convb   = (const float*)d_in[20];
    const float* fcxt_W  = (const float*)d_in[21];
    const float* fcxt_b  = (const float*)d_in[22];
    const float* fc1_W   = (const float*)d_in[23];
    const float* fc1_b   = (const float*)d_in[24];
    const float* fc2_W   = (const float*)d_in[25];
    const float* fc2_b   = (const float*)d_in[26];
    const float* out_W   = (const float*)d_in[27];
    const float* out_b   = (const float*)d_in[28];

    float *p_h, *p_agg, *p_pooled, *p_xc, *p_t1, *p_t2, *p_Wt, *p_G, *p_H;
    cudaGetSymbolAddress((void**)&p_h, g_h);
    cudaGetSymbolAddress((void**)&p_agg, g_agg);
    cudaGetSymbolAddress((void**)&p_pooled, g_pooled);
    cudaGetSymbolAddress((void**)&p_xc, g_xc);
    cudaGetSymbolAddress((void**)&p_t1, g_t1);
    cudaGetSymbolAddress((void**)&p_t2, g_t2);
    cudaGetSymbolAddress((void**)&p_Wt, g_Wt);
    cudaGetSymbolAddress((void**)&p_G, g_G);
    cudaGetSymbolAddress((void**)&p_H, g_H);

    const int EDGE_BLOCKS = (NE + 255) / 256;       // 7813
    const int AGG_BLOCKS  = (NN * 8 + 255) / 256;   // 6250

    // ---- CSR build (once per launch) ----
    zero_cnt_kernel<<<NBLK, 256>>>();
    hist_kernel<<<EDGE_BLOCKS, 256>>>(dst);
    scan1_kernel<<<NBLK, 256>>>();
    scan2_kernel<<<1, 1024>>>();
    scan3_kernel<<<NBLK, 256>>>();
    fill_kernel<<<EDGE_BLOCKS, 256>>>(src, dst);

    // ---- protein branch ----
    wtrans_kernel<<<(SEQL * 256 + 255) / 256, 256>>>(convW);
    g_kernel<<<dim3(32, NVOC), dim3(128, 8)>>>(emb, fcxt_W);
    cb_kernel<<<1, 128>>>(fcxt_W, convb, fcxt_b);
    gemm64_kernel<<<dim3((NVOC * 128) / 64, (SEQL + 63) / 64), 256>>>(
        p_Wt, p_G, nullptr, p_H, SEQL, NVOC * 128, 256, NVOC * 128, 0);
    xt_kernel<<<BB, 128>>>(target);

    // ---- graph: layer 1 ----
    proj_kernel<<<NBLK, 256>>>(x, W1a, p_h);
    agg_kernel<<<AGG_BLOCKS, 256>>>(p_h, p_agg, 0);
    nodepass_kernel<<<NBLK, 256>>>(p_agg, p_h, nullptr, b1a, W2a, b2a);
    colsum_kernel<<<625, 256>>>(p_h);
    statsfin_kernel<<<1, 32>>>(g1, be1, 0);

    // ---- graph: layers 2..5 ----
    for (int i = 0; i < 4; i++) {
        agg_kernel<<<AGG_BLOCKS, 256>>>(p_h, p_agg, 1);
        nodepass_kernel<<<NBLK, 256>>>(p_agg, p_h, Ws1 + i * 1024, bs1 + i * 32,
                                       Ws2 + i * 1024, bs2 + i * 32);
        colsum_kernel<<<625, 256>>>(p_h);
        if (i == 3) statsfin_kernel<<<64, 512>>>(gs + i * 32, bes + i * 32, 1);
        else        statsfin_kernel<<<1, 32>>>(gs + i * 32, bes + i * 32, 0);
    }

    // ---- pooling + drug head ----
    pool_kernel<<<NBLK, 256>>>(p_h, batch);
    gemm64_kernel<<<dim3(128 / 64, BB / 64), 256>>>(p_pooled, fc1xd_W, fc1xd_b,
                                                    p_xc, BB, 128, 32, 256, 1);

    // ---- joint head ----
    gemm64_kernel<<<dim3(1024 / 64, BB / 64), 256>>>(p_xc, fc1_W, fc1_b, p_t1, BB, 1024, 256, 1024, 1);
    gemm64_kernel<<<dim3(256 / 64, BB / 64), 256>>>(p_t1, fc2_W, fc2_b, p_t2, BB, 256, 1024, 256, 1);
    out_kernel<<<BB / 8, 256>>>(out_W, out_b, (float*)d_out);
}